// round 1
// baseline (speedup 1.0000x reference)
#include <cuda_runtime.h>

// Problem constants
#define B_     8
#define HEADS  8
#define D_     128
#define R_     8
#define S_     4096
#define NSLAB  (B_ * HEADS)       // 64
#define TILES  8
#define TS     (S_ / TILES)       // 512 spatial positions per tile
#define K1T    128                // threads in kernel 1 (TS/4 float4 lanes)

// ---------------- scratch (static device globals; fully rewritten each launch) ---------
__device__ float g_m[(size_t)NSLAB * S_ * R_];     // [slab][s][r]  8 MB
__device__ float g_avgp[NSLAB * TILES * D_];       // per-tile partial row sums
__device__ float g_k[NSLAB * R_];
__device__ float g_c[NSLAB];
__device__ float g_v[NSLAB * D_];                  // index == global output row
__device__ float g_attn[NSLAB * S_];               // 1 MB

// =======================================================================================
// Kernel 1: one pass over x. Produces m[slab][s][r] = sum_d Wq[h,r,d]*x[slab,d,s]
// and per-tile partial row sums (for avg). 512 CTAs x 128 threads.
// =======================================================================================
__global__ void __launch_bounds__(K1T) k1_proj(const float* __restrict__ x,
                                               const float* __restrict__ Wq)
{
    const int slab = blockIdx.x / TILES;
    const int tile = blockIdx.x % TILES;
    const int h    = slab & (HEADS - 1);
    const int t    = threadIdx.x;
    const int lane = t & 31;
    const int wid  = t >> 5;

    __shared__ __align__(16) float wqT[D_ * R_];     // [d][r]
    __shared__ float part[D_ * 4];                   // [d][warp]

    // transpose Wq head into smem: wqT[d*8+r]
    const float* wqh = Wq + (size_t)h * R_ * D_;
    #pragma unroll
    for (int i = t; i < R_ * D_; i += K1T) {
        int r = i / D_, d = i - r * D_;
        wqT[d * R_ + r] = wqh[r * D_ + d];
    }
    __syncthreads();

    // x base for this slab+tile; row d is at float4 offset d*(S_/4)
    const float4* __restrict__ xb4 =
        (const float4*)(x + (size_t)slab * D_ * S_ + (size_t)tile * TS);

    float4 acc[R_];
    #pragma unroll
    for (int r = 0; r < R_; r++) acc[r] = make_float4(0.f, 0.f, 0.f, 0.f);

    #pragma unroll 4
    for (int d = 0; d < D_; d++) {
        float4 xv = xb4[d * (S_ / 4) + t];

        const float4 w0 = *(const float4*)&wqT[d * R_];
        const float4 w1 = *(const float4*)&wqT[d * R_ + 4];

        acc[0].x += w0.x * xv.x; acc[0].y += w0.x * xv.y; acc[0].z += w0.x * xv.z; acc[0].w += w0.x * xv.w;
        acc[1].x += w0.y * xv.x; acc[1].y += w0.y * xv.y; acc[1].z += w0.y * xv.z; acc[1].w += w0.y * xv.w;
        acc[2].x += w0.z * xv.x; acc[2].y += w0.z * xv.y; acc[2].z += w0.z * xv.z; acc[2].w += w0.z * xv.w;
        acc[3].x += w0.w * xv.x; acc[3].y += w0.w * xv.y; acc[3].z += w0.w * xv.z; acc[3].w += w0.w * xv.w;
        acc[4].x += w1.x * xv.x; acc[4].y += w1.x * xv.y; acc[4].z += w1.x * xv.z; acc[4].w += w1.x * xv.w;
        acc[5].x += w1.y * xv.x; acc[5].y += w1.y * xv.y; acc[5].z += w1.y * xv.z; acc[5].w += w1.y * xv.w;
        acc[6].x += w1.z * xv.x; acc[6].y += w1.z * xv.y; acc[6].z += w1.z * xv.z; acc[6].w += w1.z * xv.w;
        acc[7].x += w1.w * xv.x; acc[7].y += w1.w * xv.y; acc[7].z += w1.w * xv.z; acc[7].w += w1.w * xv.w;

        // per-row (d) partial sum over this tile's s-positions, for avg
        float rs = (xv.x + xv.y) + (xv.z + xv.w);
        rs += __shfl_xor_sync(0xffffffffu, rs, 16);
        rs += __shfl_xor_sync(0xffffffffu, rs, 8);
        rs += __shfl_xor_sync(0xffffffffu, rs, 4);
        rs += __shfl_xor_sync(0xffffffffu, rs, 2);
        rs += __shfl_xor_sync(0xffffffffu, rs, 1);
        if (lane == 0) part[d * 4 + wid] = rs;
    }
    __syncthreads();

    // t in [0,128): finalize this tile's partial row sum
    {
        float s = (part[t * 4 + 0] + part[t * 4 + 1]) + (part[t * 4 + 2] + part[t * 4 + 3]);
        g_avgp[(slab * TILES + tile) * D_ + t] = s;
    }

    // write m: this thread owns s = tile*TS + t*4 .. +3 ; layout [s][r] (8 floats per s)
    float4* m4 = (float4*)(g_m + ((size_t)slab * S_ + (size_t)tile * TS + t * 4) * R_);
    m4[0] = make_float4(acc[0].x, acc[1].x, acc[2].x, acc[3].x);
    m4[1] = make_float4(acc[4].x, acc[5].x, acc[6].x, acc[7].x);
    m4[2] = make_float4(acc[0].y, acc[1].y, acc[2].y, acc[3].y);
    m4[3] = make_float4(acc[4].y, acc[5].y, acc[6].y, acc[7].y);
    m4[4] = make_float4(acc[0].z, acc[1].z, acc[2].z, acc[3].z);
    m4[5] = make_float4(acc[4].z, acc[5].z, acc[6].z, acc[7].z);
    m4[6] = make_float4(acc[0].w, acc[1].w, acc[2].w, acc[3].w);
    m4[7] = make_float4(acc[4].w, acc[5].w, acc[6].w, acc[7].w);
}

// =======================================================================================
// Kernel 2: per-slab tiny GEMVs: avg -> k[8], c, v[128]. 64 CTAs x 128 threads.
// =======================================================================================
__global__ void __launch_bounds__(128) k2_kv(const float* __restrict__ Wk,
                                             const float* __restrict__ bk,
                                             const float* __restrict__ Wv,
                                             const float* __restrict__ bv,
                                             const float* __restrict__ bq)
{
    const int slab = blockIdx.x;
    const int h    = slab & (HEADS - 1);
    const int t    = threadIdx.x;
    const int lane = t & 31;
    const int w    = t >> 5;

    __shared__ __align__(16) float s_avg[D_];
    __shared__ float s_k[R_];

    // finalize avg
    {
        float a = 0.f;
        #pragma unroll
        for (int i = 0; i < TILES; i++) a += g_avgp[(slab * TILES + i) * D_ + t];
        s_avg[t] = a * (1.0f / (float)S_);
    }
    __syncthreads();

    const float4 av = ((const float4*)s_avg)[lane];   // avg[lane*4 .. lane*4+3]

    // v: warp w handles e = w*32 .. w*32+31 (warp-cooperative dot products)
    for (int i = 0; i < 32; i++) {
        int e = w * 32 + i;
        float4 wv = ((const float4*)(Wv + ((size_t)h * D_ + e) * D_))[lane];
        float p = av.x * wv.x + av.y * wv.y + av.z * wv.z + av.w * wv.w;
        p += __shfl_xor_sync(0xffffffffu, p, 16);
        p += __shfl_xor_sync(0xffffffffu, p, 8);
        p += __shfl_xor_sync(0xffffffffu, p, 4);
        p += __shfl_xor_sync(0xffffffffu, p, 2);
        p += __shfl_xor_sync(0xffffffffu, p, 1);
        if (lane == 0) g_v[slab * D_ + e] = p + bv[h * D_ + e];
    }

    // k and c: warp 0
    if (w == 0) {
        for (int r = 0; r < R_; r++) {
            float4 wk = ((const float4*)(Wk + ((size_t)h * R_ + r) * D_))[lane];
            float p = av.x * wk.x + av.y * wk.y + av.z * wk.z + av.w * wk.w;
            p += __shfl_xor_sync(0xffffffffu, p, 16);
            p += __shfl_xor_sync(0xffffffffu, p, 8);
            p += __shfl_xor_sync(0xffffffffu, p, 4);
            p += __shfl_xor_sync(0xffffffffu, p, 2);
            p += __shfl_xor_sync(0xffffffffu, p, 1);
            if (lane == 0) s_k[r] = p + bk[h * R_ + r];
        }
        if (lane == 0) {
            float c = 0.f;
            #pragma unroll
            for (int r = 0; r < R_; r++) {
                float kv = s_k[r];
                c += bq[h * R_ + r] * kv;
                g_k[slab * R_ + r] = kv;
            }
            g_c[slab] = c;
        }
    }
}

// =======================================================================================
// Kernel 3: scores = m . k + c ; softmax over s=4096 ; write attn. 64 CTAs x 256 thr.
// =======================================================================================
__global__ void __launch_bounds__(256) k3_softmax()
{
    const int slab = blockIdx.x;
    const int t    = threadIdx.x;
    const int lane = t & 31;
    const int wid  = t >> 5;

    __shared__ float redmx[8];
    __shared__ float redsm[8];
    __shared__ float bmx, bsm;

    const float* kk = g_k + slab * R_;
    const float k0 = kk[0], k1 = kk[1], k2 = kk[2], k3 = kk[3];
    const float k4 = kk[4], k5 = kk[5], k6 = kk[6], k7 = kk[7];
    const float c  = g_c[slab];

    const float4* m4 = (const float4*)(g_m + (size_t)slab * S_ * R_);

    float sc[16];
    float mx = -3.4e38f;
    #pragma unroll
    for (int i = 0; i < 16; i++) {
        int s = i * 256 + t;
        float4 a = m4[s * 2];
        float4 b = m4[s * 2 + 1];
        float v = c + k0 * a.x + k1 * a.y + k2 * a.z + k3 * a.w
                    + k4 * b.x + k5 * b.y + k6 * b.z + k7 * b.w;
        sc[i] = v;
        mx = fmaxf(mx, v);
    }
    // block max
    #pragma unroll
    for (int o = 16; o; o >>= 1) mx = fmaxf(mx, __shfl_xor_sync(0xffffffffu, mx, o));
    if (lane == 0) redmx[wid] = mx;
    __syncthreads();
    if (wid == 0) {
        float v = (lane < 8) ? redmx[lane] : -3.4e38f;
        #pragma unroll
        for (int o = 4; o; o >>= 1) v = fmaxf(v, __shfl_xor_sync(0xffffffffu, v, o));
        if (lane == 0) bmx = v;
    }
    __syncthreads();
    mx = bmx;

    float tot = 0.f;
    #pragma unroll
    for (int i = 0; i < 16; i++) {
        sc[i] = __expf(sc[i] - mx);
        tot += sc[i];
    }
    // block sum
    #pragma unroll
    for (int o = 16; o; o >>= 1) tot += __shfl_xor_sync(0xffffffffu, tot, o);
    if (lane == 0) redsm[wid] = tot;
    __syncthreads();
    if (wid == 0) {
        float v = (lane < 8) ? redsm[lane] : 0.f;
        #pragma unroll
        for (int o = 4; o; o >>= 1) v += __shfl_xor_sync(0xffffffffu, v, o);
        if (lane == 0) bsm = v;
    }
    __syncthreads();
    const float inv = 1.0f / bsm;

    float* ap = g_attn + (size_t)slab * S_;
    #pragma unroll
    for (int i = 0; i < 16; i++) ap[i * 256 + t] = sc[i] * inv;
}

// =======================================================================================
// Kernel 4: out[row, s] = v[row] * attn[slab, s]. 8192 CTAs x 256 threads. Write-bound.
// =======================================================================================
__global__ void __launch_bounds__(256) k4_out(float* __restrict__ out)
{
    const int row  = blockIdx.x;      // global row in (B*C)
    const int slab = row >> 7;        // /128
    const float v  = g_v[row];
    const int t    = threadIdx.x;

    const float4* a4 = (const float4*)(g_attn + (size_t)slab * S_);
    float4* o4 = (float4*)(out + (size_t)row * S_);

    #pragma unroll
    for (int i = 0; i < 4; i++) {
        float4 a = a4[i * 256 + t];
        o4[i * 256 + t] = make_float4(v * a.x, v * a.y, v * a.z, v * a.w);
    }
}

// =======================================================================================
extern "C" void kernel_launch(void* const* d_in, const int* in_sizes, int n_in,
                              void* d_out, int out_size)
{
    const float* x  = (const float*)d_in[0];
    const float* Wq = (const float*)d_in[1];
    const float* bq = (const float*)d_in[2];
    const float* Wk = (const float*)d_in[3];
    const float* bk = (const float*)d_in[4];
    const float* Wv = (const float*)d_in[5];
    const float* bv = (const float*)d_in[6];
    float* out = (float*)d_out;

    k1_proj<<<NSLAB * TILES, K1T>>>(x, Wq);
    k2_kv<<<NSLAB, 128>>>(Wk, bk, Wv, bv, bq);
    k3_softmax<<<NSLAB, 256>>>();
    k4_out<<<B_ * 1024, 256>>>(out);
}